// round 7
// baseline (speedup 1.0000x reference)
#include <cuda_runtime.h>
#include <float.h>
#include <stdint.h>

// Problem constants
#define B_   16
#define C_   64
#define H_   256
#define W_   256
#define OC_  128
#define OH_  254
#define OW_  254

// Tiling
#define TB    128
#define TX    64
#define TY    16
#define ICC   4                 // input channels per staged chunk
#define G     8                 // output channels per accumulation pass
#define NOG   (OC_ / G)         // 16
#define NICC  (C_ / ICC)        // 16
#define NCHUNK (NOG * NICC)     // 256
#define IN_H  18                // TY + 2 halo
#define IN_W4 17                // float4 per staged row (68 floats)

// Pre-duplicated, chunk-reordered weights: [og][icc][g][ic][10] float2 (k 0..8 real, 9 pad)
#define WCHUNK (G * ICC * 10)   // 320 float2 = 2560 B per chunk
__device__ float2 g_wdup[NOG * NICC * WCHUNK];   // 640 KB scratch

__global__ void prep_weights_kernel(const float* __restrict__ w) {
    int i = blockIdx.x * blockDim.x + threadIdx.x;
    const int TOT = NOG * NICC * WCHUNK;
    if (i >= TOT) return;
    int k = i % 10;  int t = i / 10;
    int ic  = t % ICC;  t /= ICC;
    int g   = t % G;    t /= G;
    int icc = t % NICC; t /= NICC;
    int og  = t;
    float v = 0.f;
    if (k < 9) {
        int oc = og * G + g;
        int c  = icc * ICC + ic;
        v = w[((size_t)oc * C_ + c) * 9 + k];
    }
    g_wdup[i] = make_float2(v, v);
}

__device__ __forceinline__ unsigned long long packf2(float lo, float hi) {
    unsigned long long r;
    asm("mov.b64 %0, {%1,%2};" : "=l"(r) : "f"(lo), "f"(hi));
    return r;
}
__device__ __forceinline__ void fma2(unsigned long long &d,
                                     unsigned long long a, unsigned long long b) {
    asm("fma.rn.f32x2 %0, %1, %2, %0;" : "+l"(d) : "l"(a), "l"(b));
}
__device__ __forceinline__ float2 unpackf2(unsigned long long v) {
    float lo, hi;
    asm("mov.b64 {%0,%1}, %2;" : "=f"(lo), "=f"(hi) : "l"(v));
    return make_float2(lo, hi);
}
__device__ __forceinline__ void cp16(uint32_t dst, const void* src, int sz) {
    // 16B async copy; sz=0 -> zero-fill destination (halo handling)
    asm volatile("cp.async.cg.shared.global [%0], [%1], 16, %2;"
                 :: "r"(dst), "l"(src), "r"(sz));
}

__global__ __launch_bounds__(TB)
void conv3x3_bias_scale_minC_kernel(const float* __restrict__ x,
                                    const float* __restrict__ bias,
                                    float* __restrict__ out)
{
    __shared__ __align__(16) float4 s_in[2][ICC][IN_H][IN_W4];   // 2 x 19584 B
    __shared__ __align__(16) float2 s_w[2][WCHUNK];              // 2 x 2560 B

    const int b   = blockIdx.z;
    const int gx0 = blockIdx.x * TX;
    const int gy0 = blockIdx.y * TY;
    const int tid = threadIdx.x;
    const int tx  = tid & 15;              // 16 cols * 4 px
    const int ty  = tid >> 4;              // 8 rows * 2 px
    const int x0l = tx * 4;
    const int y0l = ty * 2;

    const float* xb = x + (size_t)b * C_ * H_ * W_;

    // ---- async stage of one chunk (input channels + dup'd weights) ----
    auto stage = [&](int c, int buf) {
        int icc = c & (NICC - 1);
        #pragma unroll 1
        for (int idx = tid; idx < ICC * IN_H * IN_W4; idx += TB) {
            int ic  = idx / (IN_H * IN_W4);
            int rem = idx - ic * (IN_H * IN_W4);
            int rr  = rem / IN_W4;
            int j   = rem - rr * IN_W4;
            int gy  = gy0 + rr;
            int gx  = gx0 + 4 * j;
            int ok  = (gy < H_) & (gx < W_);
            int gyc = ok ? gy : (H_ - 1);
            int gxc = ok ? gx : 0;
            const float* src = xb + ((size_t)(icc * ICC + ic) * H_ + gyc) * W_ + gxc;
            uint32_t dst = (uint32_t)__cvta_generic_to_shared(&s_in[buf][ic][rr][j]);
            cp16(dst, src, ok ? 16 : 0);
        }
        const float2* wsrc = g_wdup + (size_t)c * WCHUNK;
        #pragma unroll
        for (int idx = tid; idx < WCHUNK / 2; idx += TB) {  // 160 x 16B
            uint32_t dst = (uint32_t)__cvta_generic_to_shared(&s_w[buf][idx * 2]);
            cp16(dst, wsrc + idx * 2, 16);
        }
    };

    float m[2][4];
    #pragma unroll
    for (int r = 0; r < 2; r++)
        #pragma unroll
        for (int cc = 0; cc < 4; cc++) m[r][cc] = FLT_MAX;

    unsigned long long acc[G][2][2];

    stage(0, 0);
    asm volatile("cp.async.commit_group;");

    for (int c = 0; c < NCHUNK; ++c) {
        const int buf = c & 1;
        if (c + 1 < NCHUNK) {
            stage(c + 1, buf ^ 1);
            asm volatile("cp.async.commit_group;");
            asm volatile("cp.async.wait_group 1;");   // chunk c landed
        } else {
            asm volatile("cp.async.wait_group 0;");
        }
        __syncthreads();

        if ((c & (NICC - 1)) == 0) {                  // new og-group: init acc = bias
            int og = c >> 4;
            #pragma unroll
            for (int g = 0; g < G; g++) {
                float bv = __ldg(&bias[og * G + g]);
                unsigned long long bp = packf2(bv, bv);
                acc[g][0][0] = bp; acc[g][0][1] = bp;
                acc[g][1][0] = bp; acc[g][1][1] = bp;
            }
        }

        #pragma unroll
        for (int ic = 0; ic < ICC; ic++) {
            // P[r][k] = (in[r][x0l+k], in[r][x0l+k+1])
            unsigned long long P[4][5];
            #pragma unroll
            for (int r = 0; r < 4; r++) {
                const float* row = (const float*)&s_in[buf][ic][y0l + r][0];
                float4 v = *(const float4*)(row + x0l);
                float2 u = *(const float2*)(row + x0l + 4);
                P[r][0] = packf2(v.x, v.y);
                P[r][1] = packf2(v.y, v.z);
                P[r][2] = packf2(v.z, v.w);
                P[r][3] = packf2(v.w, u.x);
                P[r][4] = packf2(u.x, u.y);
            }
            #pragma unroll
            for (int g = 0; g < G; g++) {
                const float2* wb = &s_w[buf][(g * ICC + ic) * 10];
                ulonglong2 w01 = *(const ulonglong2*)(wb + 0);   // LDS.128
                ulonglong2 w23 = *(const ulonglong2*)(wb + 2);
                ulonglong2 w45 = *(const ulonglong2*)(wb + 4);
                ulonglong2 w67 = *(const ulonglong2*)(wb + 6);
                unsigned long long w8 = *(const unsigned long long*)(wb + 8);
                unsigned long long wp[9] = { w01.x, w01.y, w23.x, w23.y,
                                             w45.x, w45.y, w67.x, w67.y, w8 };
                #pragma unroll
                for (int r = 0; r < 2; r++)
                    #pragma unroll
                    for (int ky = 0; ky < 3; ky++)
                        #pragma unroll
                        for (int kx = 0; kx < 3; kx++)
                            #pragma unroll
                            for (int p = 0; p < 2; p++)
                                fma2(acc[g][r][p], P[r + ky][2 * p + kx], wp[ky * 3 + kx]);
            }
        }

        if ((c & (NICC - 1)) == (NICC - 1)) {         // og-group done: fold channel-min
            #pragma unroll
            for (int g = 0; g < G; g++)
                #pragma unroll
                for (int r = 0; r < 2; r++)
                    #pragma unroll
                    for (int p = 0; p < 2; p++) {
                        float2 v = unpackf2(acc[g][r][p]);
                        m[r][2 * p]     = fminf(m[r][2 * p],     v.x);
                        m[r][2 * p + 1] = fminf(m[r][2 * p + 1], v.y);
                    }
        }
        __syncthreads();   // all done reading buf before it is restaged
    }

    // y = (conv + bias) * 2; positive scale commutes with min
    #pragma unroll
    for (int r = 0; r < 2; r++) {
        int oy = gy0 + y0l + r;
        if (oy >= OH_) continue;
        #pragma unroll
        for (int cc = 0; cc < 4; cc++) {
            int ox = gx0 + x0l + cc;
            if (ox >= OW_) continue;
            out[((size_t)b * OH_ + oy) * OW_ + ox] = 2.0f * m[r][cc];
        }
    }
}

extern "C" void kernel_launch(void* const* d_in, const int* in_sizes, int n_in,
                              void* d_out, int out_size)
{
    const float* x    = (const float*)d_in[0];   // (16,64,256,256)
    const float* w    = (const float*)d_in[1];   // (128,64,3,3)
    const float* bias = (const float*)d_in[2];   // (128,)
    float* out = (float*)d_out;                  // (16,1,254,254)

    const int TOT = NOG * NICC * WCHUNK;
    prep_weights_kernel<<<(TOT + 255) / 256, 256>>>(w);

    dim3 grid((OW_ + TX - 1) / TX,   // 4
              (OH_ + TY - 1) / TY,   // 16
              B_);                   // 16
    conv3x3_bias_scale_minC_kernel<<<grid, TB>>>(x, bias, out);
    (void)in_sizes; (void)n_in; (void)out_size;
}

// round 9
// speedup vs baseline: 1.0007x; 1.0007x over previous
#include <cuda_runtime.h>
#include <float.h>
#include <stdint.h>

// Problem constants
#define B_   16
#define C_   64
#define H_   256
#define W_   256
#define OC_  128
#define OH_  254
#define OW_  254

// Tiling
#define TB    128
#define TX    64
#define TY    16
#define ICC   4                 // input channels per staged chunk
#define G     8                 // output channels per accumulation pass
#define NOG   (OC_ / G)         // 16
#define NICC  (C_ / ICC)        // 16
#define NCHUNK (NOG * NICC)     // 256
#define IN_H  18                // TY + 2 halo
#define IN_W4 17                // float4 per staged row (68 floats)

// Pre-duplicated, chunk-reordered weights: [og][icc][g][ic][10] float2 (k 0..8 real, 9 pad)
#define WCHUNK (G * ICC * 10)   // 320 float2 = 2560 B per chunk
__device__ float2 g_wdup[NOG * NICC * WCHUNK];   // 640 KB scratch

__global__ void prep_weights_kernel(const float* __restrict__ w) {
    int i = blockIdx.x * blockDim.x + threadIdx.x;
    const int TOT = NOG * NICC * WCHUNK;
    if (i >= TOT) return;
    int k = i % 10;  int t = i / 10;
    int ic  = t % ICC;  t /= ICC;
    int g   = t % G;    t /= G;
    int icc = t % NICC; t /= NICC;
    int og  = t;
    float v = 0.f;
    if (k < 9) {
        int oc = og * G + g;
        int c  = icc * ICC + ic;
        v = w[((size_t)oc * C_ + c) * 9 + k];
    }
    g_wdup[i] = make_float2(v, v);
}

__device__ __forceinline__ unsigned long long packf2(float lo, float hi) {
    unsigned long long r;
    asm("mov.b64 %0, {%1,%2};" : "=l"(r) : "f"(lo), "f"(hi));
    return r;
}
__device__ __forceinline__ void fma2(unsigned long long &d,
                                     unsigned long long a, unsigned long long b) {
    asm("fma.rn.f32x2 %0, %1, %2, %0;" : "+l"(d) : "l"(a), "l"(b));
}
__device__ __forceinline__ float2 unpackf2(unsigned long long v) {
    float lo, hi;
    asm("mov.b64 {%0,%1}, %2;" : "=f"(lo), "=f"(hi) : "l"(v));
    return make_float2(lo, hi);
}
__device__ __forceinline__ void cp16(uint32_t dst, const void* src, int sz) {
    // 16B async copy; sz=0 -> zero-fill destination (halo handling)
    asm volatile("cp.async.cg.shared.global [%0], [%1], 16, %2;"
                 :: "r"(dst), "l"(src), "r"(sz));
}

__global__ __launch_bounds__(TB)
void conv3x3_bias_scale_minC_kernel(const float* __restrict__ x,
                                    const float* __restrict__ bias,
                                    float* __restrict__ out)
{
    __shared__ __align__(16) float4 s_in[2][ICC][IN_H][IN_W4];   // 2 x 19584 B
    __shared__ __align__(16) float2 s_w[2][WCHUNK];              // 2 x 2560 B

    const int b   = blockIdx.z;
    const int gx0 = blockIdx.x * TX;
    const int gy0 = blockIdx.y * TY;
    const int tid = threadIdx.x;
    const int tx  = tid & 15;              // 16 cols * 4 px
    const int ty  = tid >> 4;              // 8 rows * 2 px
    const int x0l = tx * 4;
    const int y0l = ty * 2;

    const float* xb = x + (size_t)b * C_ * H_ * W_;

    // ---- async stage of one chunk (input channels + dup'd weights) ----
    auto stage = [&](int c, int buf) {
        int icc = c & (NICC - 1);
        #pragma unroll 1
        for (int idx = tid; idx < ICC * IN_H * IN_W4; idx += TB) {
            int ic  = idx / (IN_H * IN_W4);
            int rem = idx - ic * (IN_H * IN_W4);
            int rr  = rem / IN_W4;
            int j   = rem - rr * IN_W4;
            int gy  = gy0 + rr;
            int gx  = gx0 + 4 * j;
            int ok  = (gy < H_) & (gx < W_);
            int gyc = ok ? gy : (H_ - 1);
            int gxc = ok ? gx : 0;
            const float* src = xb + ((size_t)(icc * ICC + ic) * H_ + gyc) * W_ + gxc;
            uint32_t dst = (uint32_t)__cvta_generic_to_shared(&s_in[buf][ic][rr][j]);
            cp16(dst, src, ok ? 16 : 0);
        }
        const float2* wsrc = g_wdup + (size_t)c * WCHUNK;
        #pragma unroll
        for (int idx = tid; idx < WCHUNK / 2; idx += TB) {  // 160 x 16B
            uint32_t dst = (uint32_t)__cvta_generic_to_shared(&s_w[buf][idx * 2]);
            cp16(dst, wsrc + idx * 2, 16);
        }
    };

    float m[2][4];
    #pragma unroll
    for (int r = 0; r < 2; r++)
        #pragma unroll
        for (int cc = 0; cc < 4; cc++) m[r][cc] = FLT_MAX;

    unsigned long long acc[G][2][2];

    stage(0, 0);
    asm volatile("cp.async.commit_group;");

    for (int c = 0; c < NCHUNK; ++c) {
        const int buf = c & 1;
        if (c + 1 < NCHUNK) {
            stage(c + 1, buf ^ 1);
            asm volatile("cp.async.commit_group;");
            asm volatile("cp.async.wait_group 1;");   // chunk c landed
        } else {
            asm volatile("cp.async.wait_group 0;");
        }
        __syncthreads();

        if ((c & (NICC - 1)) == 0) {                  // new og-group: init acc = bias
            int og = c >> 4;
            #pragma unroll
            for (int g = 0; g < G; g++) {
                float bv = __ldg(&bias[og * G + g]);
                unsigned long long bp = packf2(bv, bv);
                acc[g][0][0] = bp; acc[g][0][1] = bp;
                acc[g][1][0] = bp; acc[g][1][1] = bp;
            }
        }

        #pragma unroll
        for (int ic = 0; ic < ICC; ic++) {
            // P[r][k] = (in[r][x0l+k], in[r][x0l+k+1])
            unsigned long long P[4][5];
            #pragma unroll
            for (int r = 0; r < 4; r++) {
                const float* row = (const float*)&s_in[buf][ic][y0l + r][0];
                float4 v = *(const float4*)(row + x0l);
                float2 u = *(const float2*)(row + x0l + 4);
                P[r][0] = packf2(v.x, v.y);
                P[r][1] = packf2(v.y, v.z);
                P[r][2] = packf2(v.z, v.w);
                P[r][3] = packf2(v.w, u.x);
                P[r][4] = packf2(u.x, u.y);
            }
            #pragma unroll
            for (int g = 0; g < G; g++) {
                const float2* wb = &s_w[buf][(g * ICC + ic) * 10];
                ulonglong2 w01 = *(const ulonglong2*)(wb + 0);   // LDS.128
                ulonglong2 w23 = *(const ulonglong2*)(wb + 2);
                ulonglong2 w45 = *(const ulonglong2*)(wb + 4);
                ulonglong2 w67 = *(const ulonglong2*)(wb + 6);
                unsigned long long w8 = *(const unsigned long long*)(wb + 8);
                unsigned long long wp[9] = { w01.x, w01.y, w23.x, w23.y,
                                             w45.x, w45.y, w67.x, w67.y, w8 };
                #pragma unroll
                for (int r = 0; r < 2; r++)
                    #pragma unroll
                    for (int ky = 0; ky < 3; ky++)
                        #pragma unroll
                        for (int kx = 0; kx < 3; kx++)
                            #pragma unroll
                            for (int p = 0; p < 2; p++)
                                fma2(acc[g][r][p], P[r + ky][2 * p + kx], wp[ky * 3 + kx]);
            }
        }

        if ((c & (NICC - 1)) == (NICC - 1)) {         // og-group done: fold channel-min
            #pragma unroll
            for (int g = 0; g < G; g++)
                #pragma unroll
                for (int r = 0; r < 2; r++)
                    #pragma unroll
                    for (int p = 0; p < 2; p++) {
                        float2 v = unpackf2(acc[g][r][p]);
                        m[r][2 * p]     = fminf(m[r][2 * p],     v.x);
                        m[r][2 * p + 1] = fminf(m[r][2 * p + 1], v.y);
                    }
        }
        __syncthreads();   // all done reading buf before it is restaged
    }

    // y = (conv + bias) * 2; positive scale commutes with min
    #pragma unroll
    for (int r = 0; r < 2; r++) {
        int oy = gy0 + y0l + r;
        if (oy >= OH_) continue;
        #pragma unroll
        for (int cc = 0; cc < 4; cc++) {
            int ox = gx0 + x0l + cc;
            if (ox >= OW_) continue;
            out[((size_t)b * OH_ + oy) * OW_ + ox] = 2.0f * m[r][cc];
        }
    }
}

extern "C" void kernel_launch(void* const* d_in, const int* in_sizes, int n_in,
                              void* d_out, int out_size)
{
    const float* x    = (const float*)d_in[0];   // (16,64,256,256)
    const float* w    = (const float*)d_in[1];   // (128,64,3,3)
    const float* bias = (const float*)d_in[2];   // (128,)
    float* out = (float*)d_out;                  // (16,1,254,254)

    const int TOT = NOG * NICC * WCHUNK;
    prep_weights_kernel<<<(TOT + 255) / 256, 256>>>(w);

    dim3 grid((OW_ + TX - 1) / TX,   // 4
              (OH_ + TY - 1) / TY,   // 16
              B_);                   // 16
    conv3x3_bias_scale_minC_kernel<<<grid, TB>>>(x, bias, out);
    (void)in_sizes; (void)n_in; (void)out_size;
}

// round 11
// speedup vs baseline: 2.9153x; 2.9134x over previous
#include <cuda_runtime.h>
#include <cuda_bf16.h>
#include <float.h>
#include <stdint.h>

#define B_   16
#define C_   64
#define H_   256
#define W_   256
#define OC_  128
#define OH_  254
#define OW_  254

#define TW   16      // tile width (px)
#define TH   8       // tile height (px) -> M = 128
#define PW   20      // patch width incl. halo + pad
#define PH   10      // patch height incl. halo
#define TB   256     // 8 warps

// patch smem: [half][y][x][ic] bf16, x-stride 144B (128B payload + 16B pad)
#define XSTRIDE   144
#define YSTRIDE   (PW * XSTRIDE)          // 2880
#define PATCH_HALF (PH * YSTRIDE)          // 28800
#define SM_BIAS   0                        // 512 B
#define SM_RED    512                      // 128 px * 2 * 4B = 1024 B
#define SM_PATCH  1536
#define SM_B      (SM_PATCH + 2 * PATCH_HALF + 256)   // 59392
#define B_POS     32768                    // one position: 2 halves * 16 KB
#define SMEM_TOTAL (SM_B + 2 * B_POS)      // 124928

// weights in per-lane fragment order: [pos][half][kc][ntile][lane][4] bf16
__device__ __align__(16) __nv_bfloat16 g_wfrag[9 * 2 * 4 * 16 * 32 * 4];

__global__ void prep_weights_kernel(const float* __restrict__ w) {
    int i = blockIdx.x * blockDim.x + threadIdx.x;   // 36864 entries
    if (i >= 9 * 2 * 4 * 16 * 32) return;
    int lane = i & 31;
    int nt   = (i >> 5) & 15;
    int kc   = (i >> 9) & 3;
    int half = (i >> 11) & 1;
    int pos  = i >> 12;
    int oc   = nt * 8 + (lane >> 2);
    int kk0  = (lane & 3) * 2;
    int ics[4] = { kc*16 + kk0, kc*16 + kk0 + 1, kc*16 + kk0 + 8, kc*16 + kk0 + 9 };
    __nv_bfloat16 outv[4];
    #pragma unroll
    for (int j = 0; j < 4; j++) {
        float v = w[((size_t)oc * C_ + ics[j]) * 9 + pos];
        __nv_bfloat16 hi = __float2bfloat16(v);
        if (half == 0) outv[j] = hi;
        else           outv[j] = __float2bfloat16(v - __bfloat162float(hi));
    }
    *(uint2*)(&g_wfrag[(size_t)i * 4]) = *(uint2*)outv;
}

__device__ __forceinline__ void mma16816(float* d, const uint32_t* a, const uint32_t* b) {
    asm volatile(
        "mma.sync.aligned.m16n8k16.row.col.f32.bf16.bf16.f32 "
        "{%0,%1,%2,%3},{%4,%5,%6,%7},{%8,%9},{%0,%1,%2,%3};"
        : "+f"(d[0]), "+f"(d[1]), "+f"(d[2]), "+f"(d[3])
        : "r"(a[0]), "r"(a[1]), "r"(a[2]), "r"(a[3]), "r"(b[0]), "r"(b[1]));
}
__device__ __forceinline__ void ldmx4(uint32_t* r, uint32_t addr) {
    asm volatile("ldmatrix.sync.aligned.m8n8.x4.shared.b16 {%0,%1,%2,%3},[%4];"
                 : "=r"(r[0]), "=r"(r[1]), "=r"(r[2]), "=r"(r[3]) : "r"(addr));
}
__device__ __forceinline__ void cp16(uint32_t dst, const void* src) {
    asm volatile("cp.async.cg.shared.global [%0], [%1], 16;" :: "r"(dst), "l"(src));
}

__global__ __launch_bounds__(TB, 1)
void conv_mma_min_kernel(const float* __restrict__ x,
                         const float* __restrict__ bias,
                         float* __restrict__ out)
{
    extern __shared__ __align__(128) char smem[];
    const uint32_t sb = (uint32_t)__cvta_generic_to_shared(smem);
    const int tid  = threadIdx.x;
    const int lane = tid & 31;
    const int warp = tid >> 5;
    const int wm   = warp >> 1;           // 0..3 : M slice (32 px)
    const int wn   = warp & 1;            // 0..1 : N half (64 oc)

    const int gx0 = blockIdx.x * TW;
    const int gy0 = blockIdx.y * TH;
    const int bt  = blockIdx.z;
    const float* xb = x + (size_t)bt * C_ * H_ * W_;

    if (tid < 32)
        *(float4*)(smem + SM_BIAS + tid * 16) = *(const float4*)(bias + tid * 4);

    // ---- stage input patch: fp32 -> bf16 hi/lo ----
    for (int i = tid; i < C_ * PH * PW; i += TB) {
        int ic  = i / (PH * PW);
        int pix = i - ic * (PH * PW);
        int yy  = pix / PW;
        int xx  = pix - yy * PW;
        int gy = gy0 + yy, gx = gx0 + xx;
        float v = 0.f;
        if (gy < H_ && gx < W_)
            v = __ldg(xb + ((size_t)ic * H_ + gy) * W_ + gx);
        __nv_bfloat16 hi = __float2bfloat16(v);
        __nv_bfloat16 lo = __float2bfloat16(v - __bfloat162float(hi));
        int off = yy * YSTRIDE + xx * XSTRIDE + ic * 2;
        *(__nv_bfloat16*)(smem + SM_PATCH + off)              = hi;
        *(__nv_bfloat16*)(smem + SM_PATCH + PATCH_HALF + off) = lo;
    }

    // ---- prefetch B(0) (both halves, fragment-ordered) ----
    {
        const char* src = (const char*)g_wfrag;          // pos 0
        for (int g = tid; g < B_POS / 16; g += TB)
            cp16(sb + SM_B + g * 16, src + g * 16);
        asm volatile("cp.async.commit_group;");
    }

    float d[2][8][4];
    #pragma unroll
    for (int mt = 0; mt < 2; mt++)
        #pragma unroll
        for (int nt = 0; nt < 8; nt++)
            #pragma unroll
            for (int j = 0; j < 4; j++) d[mt][nt][j] = 0.f;

    // A-lane geometry (constant across positions/kc)
    const int arow = 2 * wm;                 // py base for mt=0
    const int acol = lane & 15;              // px within tile
    const uint32_t asel = (uint32_t)(lane >> 4) * 16;

    #pragma unroll 1
    for (int c = 0; c < 9; ++c) {
        const int buf = c & 1;
        asm volatile("cp.async.wait_group 0;");
        __syncthreads();                     // B(c) + (c==0) patch visible

        if (c < 8) {                         // prefetch B(c+1) into other buffer
            const char* src = (const char*)g_wfrag + (size_t)(c + 1) * B_POS;
            uint32_t bb = sb + SM_B + (buf ^ 1) * B_POS;
            for (int g = tid; g < B_POS / 16; g += TB)
                cp16(bb + g * 16, src + g * 16);
            asm volatile("cp.async.commit_group;");
        }

        const int ky = c / 3, kx = c - 3 * ky;
        const uint32_t abase = sb + SM_PATCH
                             + (uint32_t)(arow + ky) * YSTRIDE
                             + (uint32_t)(acol + kx) * XSTRIDE + asel;
        const uint32_t bbase = sb + SM_B + buf * B_POS
                             + (uint32_t)(wn * 8 * 32 + lane) * 8;

        #pragma unroll
        for (int kc = 0; kc < 4; kc++) {
            uint32_t ah[2][4], al[2][4];
            ldmx4(ah[0], abase + kc * 32);
            ldmx4(ah[1], abase + kc * 32 + YSTRIDE);
            ldmx4(al[0], abase + kc * 32 + PATCH_HALF);
            ldmx4(al[1], abase + kc * 32 + PATCH_HALF + YSTRIDE);
            #pragma unroll
            for (int nt = 0; nt < 8; nt++) {
                uint32_t bh[2], bl[2];
                uint32_t boff = bbase + (uint32_t)(kc * 16 + nt) * 256;
                *(uint2*)bh = *(const uint2*)(smem + (boff - sb));
                *(uint2*)bl = *(const uint2*)(smem + (boff - sb) + 16384);
                mma16816(d[0][nt], ah[0], bh);   // H*H
                mma16816(d[1][nt], ah[1], bh);
                mma16816(d[0][nt], ah[0], bl);   // H*L
                mma16816(d[1][nt], ah[1], bl);
                mma16816(d[0][nt], al[0], bh);   // L*H
                mma16816(d[1][nt], al[1], bh);
            }
        }
    }

    // ---- epilogue: min over 128 oc (+bias), then *2 ----
    const int q = lane & 3;
    const int r = lane >> 2;
    float bpair[8][2];
    #pragma unroll
    for (int nt = 0; nt < 8; nt++) {
        int c0 = wn * 64 + nt * 8 + q * 2;
        const float* bs = (const float*)(smem + SM_BIAS);
        bpair[nt][0] = bs[c0];
        bpair[nt][1] = bs[c0 + 1];
    }
    #pragma unroll
    for (int mt = 0; mt < 2; mt++) {
        #pragma unroll
        for (int rh = 0; rh < 2; rh++) {
            float m = FLT_MAX;
            #pragma unroll
            for (int nt = 0; nt < 8; nt++) {
                m = fminf(m, d[mt][nt][2 * rh]     + bpair[nt][0]);
                m = fminf(m, d[mt][nt][2 * rh + 1] + bpair[nt][1]);
            }
            m = fminf(m, __shfl_xor_sync(0xffffffffu, m, 1));
            m = fminf(m, __shfl_xor_sync(0xffffffffu, m, 2));
            if (q == 0) {
                int px = r + 8 * rh;
                int py = 2 * wm + mt;
                ((float*)(smem + SM_RED))[(py * 16 + px) * 2 + wn] = m;
            }
        }
    }
    __syncthreads();
    if (tid < 128) {
        int py = tid >> 4, px = tid & 15;
        int oy = gy0 + py, ox = gx0 + px;
        if (oy < OH_ && ox < OW_) {
            const float* red = (const float*)(smem + SM_RED);
            float m = fminf(red[tid * 2], red[tid * 2 + 1]);
            out[((size_t)bt * OH_ + oy) * OW_ + ox] = 2.0f * m;
        }
    }
}

extern "C" void kernel_launch(void* const* d_in, const int* in_sizes, int n_in,
                              void* d_out, int out_size)
{
    const float* x    = (const float*)d_in[0];   // (16,64,256,256)
    const float* w    = (const float*)d_in[1];   // (128,64,3,3)
    const float* bias = (const float*)d_in[2];   // (128,)
    float* out = (float*)d_out;                  // (16,1,254,254)

    cudaFuncSetAttribute(conv_mma_min_kernel,
                         cudaFuncAttributeMaxDynamicSharedMemorySize, SMEM_TOTAL);

    prep_weights_kernel<<<(9 * 2 * 4 * 16 * 32 + 255) / 256, 256>>>(w);

    dim3 grid(16, 32, B_);   // x-tiles, y-tiles, batch
    conv_mma_min_kernel<<<grid, TB, SMEM_TOTAL>>>(x, bias, out);
    (void)in_sizes; (void)n_in; (void)out_size;
}

// round 13
// speedup vs baseline: 3.6986x; 1.2687x over previous
#include <cuda_runtime.h>
#include <cuda_bf16.h>
#include <float.h>
#include <stdint.h>

#define B_   16
#define C_   64
#define H_   256
#define W_   256
#define OC_  128
#define OH_  254
#define OW_  254

#define TW   16      // tile width (px)
#define TH   8       // tile height (px) -> M = 128
#define PW   20      // patch width incl. halo + pad
#define PH   10      // patch height incl. halo
#define TB   256     // 8 warps

// patch smem: [half][y][x][ic] bf16, x-stride 144B (128B payload + 16B pad)
#define XSTRIDE    144
#define YSTRIDE    (PW * XSTRIDE)          // 2880
#define PATCH_HALF (PH * YSTRIDE)          // 28800
#define SM_BIAS    0                        // 512 B
#define SM_RED     512                      // 128 px * 2 * 4B = 1024 B
#define SM_PATCH   1536
#define SMEM_TOTAL (SM_PATCH + 2 * PATCH_HALF)   // 59136 -> 2 CTAs/SM

// weights in per-lane fragment order: [pos][half][kc][ntile(16)][lane(32)][4] bf16
#define W_ELEMS (9 * 2 * 4 * 16 * 32 * 4)
__device__ __align__(16) __nv_bfloat16 g_wfrag[W_ELEMS];

__global__ void prep_weights_kernel(const float* __restrict__ w) {
    int i = blockIdx.x * blockDim.x + threadIdx.x;   // 36864 fragments
    if (i >= 9 * 2 * 4 * 16 * 32) return;
    int lane = i & 31;
    int nt   = (i >> 5) & 15;
    int kc   = (i >> 9) & 3;
    int half = (i >> 11) & 1;
    int pos  = i >> 12;
    int oc   = nt * 8 + (lane >> 2);
    int kk0  = (lane & 3) * 2;
    int ics[4] = { kc*16 + kk0, kc*16 + kk0 + 1, kc*16 + kk0 + 8, kc*16 + kk0 + 9 };
    __nv_bfloat16 outv[4];
    #pragma unroll
    for (int j = 0; j < 4; j++) {
        float v = w[((size_t)oc * C_ + ics[j]) * 9 + pos];
        __nv_bfloat16 hi = __float2bfloat16(v);
        if (half == 0) outv[j] = hi;
        else           outv[j] = __float2bfloat16(v - __bfloat162float(hi));
    }
    *(uint2*)(&g_wfrag[(size_t)i * 4]) = *(uint2*)outv;
}

__device__ __forceinline__ void mma16816(float* d, const uint32_t* a, const uint32_t* b) {
    asm volatile(
        "mma.sync.aligned.m16n8k16.row.col.f32.bf16.bf16.f32 "
        "{%0,%1,%2,%3},{%4,%5,%6,%7},{%8,%9},{%0,%1,%2,%3};"
        : "+f"(d[0]), "+f"(d[1]), "+f"(d[2]), "+f"(d[3])
        : "r"(a[0]), "r"(a[1]), "r"(a[2]), "r"(a[3]), "r"(b[0]), "r"(b[1]));
}
__device__ __forceinline__ void ldmx4(uint32_t* r, uint32_t addr) {
    asm volatile("ldmatrix.sync.aligned.m8n8.x4.shared.b16 {%0,%1,%2,%3},[%4];"
                 : "=r"(r[0]), "=r"(r[1]), "=r"(r[2]), "=r"(r[3]) : "r"(addr));
}

__global__ __launch_bounds__(TB, 2)
void conv_mma_min_kernel(const float* __restrict__ x,
                         const float* __restrict__ bias,
                         float* __restrict__ out)
{
    extern __shared__ __align__(128) char smem[];
    const uint32_t sb = (uint32_t)__cvta_generic_to_shared(smem);
    const int tid  = threadIdx.x;
    const int lane = tid & 31;
    const int warp = tid >> 5;
    const int wm   = warp >> 1;           // 0..3 : M slice (32 px)
    const int wn   = warp & 1;            // 0..1 : N half (64 oc)

    const int gx0 = blockIdx.x * TW;
    const int gy0 = blockIdx.y * TH;
    const int bt  = blockIdx.z;
    const float* xb = x + (size_t)bt * C_ * H_ * W_;

    if (tid < 32)
        *(float4*)(smem + SM_BIAS + tid * 16) = *(const float4*)(bias + tid * 4);

    // ---- stage input patch: fp32 -> bf16 hi/lo ----
    for (int i = tid; i < C_ * PH * PW; i += TB) {
        int ic  = i / (PH * PW);
        int pix = i - ic * (PH * PW);
        int yy  = pix / PW;
        int xx  = pix - yy * PW;
        int gy = gy0 + yy, gx = gx0 + xx;
        float v = 0.f;
        if (gy < H_ && gx < W_)
            v = __ldg(xb + ((size_t)ic * H_ + gy) * W_ + gx);
        __nv_bfloat16 hi = __float2bfloat16(v);
        __nv_bfloat16 lo = __float2bfloat16(v - __bfloat162float(hi));
        int off = yy * YSTRIDE + xx * XSTRIDE + ic * 2;
        *(__nv_bfloat16*)(smem + SM_PATCH + off)              = hi;
        *(__nv_bfloat16*)(smem + SM_PATCH + PATCH_HALF + off) = lo;
    }
    __syncthreads();                       // patch visible; only sync before epilogue

    float d[2][8][4];
    #pragma unroll
    for (int mt = 0; mt < 2; mt++)
        #pragma unroll
        for (int nt = 0; nt < 8; nt++)
            #pragma unroll
            for (int j = 0; j < 4; j++) d[mt][nt][j] = 0.f;

    // A-lane geometry (constant across positions/kc)
    const int arow = 2 * wm;
    const int acol = lane & 15;
    const uint32_t asel = (uint32_t)(lane >> 4) * 16;

    #pragma unroll 1
    for (int c = 0; c < 9; ++c) {
        const int ky = c / 3, kx = c - 3 * ky;
        const uint32_t abase = sb + SM_PATCH
                             + (uint32_t)(arow + ky) * YSTRIDE
                             + (uint32_t)(acol + kx) * XSTRIDE + asel;
        // B fragments straight from L2-resident global (coalesced LDG.64)
        const __nv_bfloat16* bp = g_wfrag
            + (((size_t)c * 2 * 4 + 0) * 16 + wn * 8) * 32 * 4 + lane * 4;

        #pragma unroll
        for (int kc = 0; kc < 4; kc++) {
            uint32_t ah[2][4], al[2][4];
            ldmx4(ah[0], abase + kc * 32);
            ldmx4(ah[1], abase + kc * 32 + YSTRIDE);
            ldmx4(al[0], abase + kc * 32 + PATCH_HALF);
            ldmx4(al[1], abase + kc * 32 + PATCH_HALF + YSTRIDE);
            const __nv_bfloat16* bk = bp + (size_t)kc * 16 * 32 * 4;
            #pragma unroll
            for (int nt = 0; nt < 8; nt++) {
                uint32_t bh[2], bl[2];
                *(uint2*)bh = __ldg((const uint2*)(bk + nt * 128));
                *(uint2*)bl = __ldg((const uint2*)(bk + nt * 128 + 8192));
                mma16816(d[0][nt], ah[0], bh);   // H*H
                mma16816(d[1][nt], ah[1], bh);
                mma16816(d[0][nt], ah[0], bl);   // H*L
                mma16816(d[1][nt], ah[1], bl);
                mma16816(d[0][nt], al[0], bh);   // L*H
                mma16816(d[1][nt], al[1], bh);
            }
        }
    }

    // ---- epilogue: min over 128 oc (+bias), then *2 ----
    const int q = lane & 3;
    const int r = lane >> 2;
    float bpair[8][2];
    #pragma unroll
    for (int nt = 0; nt < 8; nt++) {
        int c0 = wn * 64 + nt * 8 + q * 2;
        const float* bs = (const float*)(smem + SM_BIAS);
        bpair[nt][0] = bs[c0];
        bpair[nt][1] = bs[c0 + 1];
    }
    #pragma unroll
    for (int mt = 0; mt < 2; mt++) {
        #pragma unroll
        for (int rh = 0; rh < 2; rh++) {
            float m = FLT_MAX;
            #pragma unroll
            for (int nt = 0; nt < 8; nt++) {
                m = fminf(m, d[mt][nt][2 * rh]     + bpair[nt][0]);
                m = fminf(m, d[mt][nt][2 * rh + 1] + bpair[nt][1]);
            }
            m = fminf(m, __shfl_xor_sync(0xffffffffu, m, 1));
            m = fminf(m, __shfl_xor_sync(0xffffffffu, m, 2));
            if (q == 0) {
                int px = r + 8 * rh;
                int py = 2 * wm + mt;
                ((float*)(smem + SM_RED))[(py * 16 + px) * 2 + wn] = m;
            }
        }
    }
    __syncthreads();
    if (tid < 128) {
        int py = tid >> 4, px = tid & 15;
        int oy = gy0 + py, ox = gx0 + px;
        if (oy < OH_ && ox < OW_) {
            const float* red = (const float*)(smem + SM_RED);
            float m = fminf(red[tid * 2], red[tid * 2 + 1]);
            out[((size_t)bt * OH_ + oy) * OW_ + ox] = 2.0f * m;
        }
    }
}

extern "C" void kernel_launch(void* const* d_in, const int* in_sizes, int n_in,
                              void* d_out, int out_size)
{
    const float* x    = (const float*)d_in[0];   // (16,64,256,256)
    const float* w    = (const float*)d_in[1];   // (128,64,3,3)
    const float* bias = (const float*)d_in[2];   // (128,)
    float* out = (float*)d_out;                  // (16,1,254,254)

    cudaFuncSetAttribute(conv_mma_min_kernel,
                         cudaFuncAttributeMaxDynamicSharedMemorySize, SMEM_TOTAL);

    prep_weights_kernel<<<(9 * 2 * 4 * 16 * 32 + 255) / 256, 256>>>(w);

    dim3 grid(16, 32, B_);   // x-tiles, y-tiles, batch
    conv_mma_min_kernel<<<grid, TB, SMEM_TOTAL>>>(x, bias, out);
    (void)in_sizes; (void)n_in; (void)out_size;
}

// round 14
// speedup vs baseline: 6.1412x; 1.6604x over previous
#include <cuda_runtime.h>
#include <cuda_fp16.h>
#include <float.h>
#include <stdint.h>

#define B_   16
#define C_   64
#define H_   256
#define W_   256
#define OC_  128
#define OH_  254
#define OW_  254

#define TW   16      // tile width (px)
#define TH   8       // tile height (px) -> M = 128
#define PW   20      // patch width incl. halo + pad
#define PH   10      // patch height incl. halo
#define TB   256     // 8 warps

// patch smem: [y][x][ic] fp16, x-stride 144B (128B payload + 16B pad vs bank camping)
#define XSTRIDE    144
#define YSTRIDE    (PW * XSTRIDE)          // 2880
#define PATCH_SZ   (PH * YSTRIDE)          // 28800
#define SM_BIAS    0                       // 512 B
#define SM_RED     512                     // 128 px * 2 * 4B
#define SM_PATCH   1536
#define SMEM_TOTAL (SM_PATCH + PATCH_SZ)   // 30336 -> smem no longer the occ limiter

// weights fp16, per-lane fragment order: [pos][kc(4)][nt(16)][lane(32)][4]
#define W_FRAGS (9 * 4 * 16 * 32)
__device__ __align__(16) __half g_wfrag[W_FRAGS * 4];

__global__ void prep_weights_kernel(const float* __restrict__ w) {
    int i = blockIdx.x * blockDim.x + threadIdx.x;
    if (i >= W_FRAGS) return;
    int lane = i & 31;
    int nt   = (i >> 5) & 15;
    int kc   = (i >> 9) & 3;
    int pos  = i >> 11;
    int oc   = nt * 8 + (lane >> 2);
    int kk0  = (lane & 3) * 2;
    int ics[4] = { kc*16 + kk0, kc*16 + kk0 + 1, kc*16 + kk0 + 8, kc*16 + kk0 + 9 };
    __half outv[4];
    #pragma unroll
    for (int j = 0; j < 4; j++)
        outv[j] = __float2half(w[((size_t)oc * C_ + ics[j]) * 9 + pos]);
    *(uint2*)(&g_wfrag[(size_t)i * 4]) = *(uint2*)outv;
}

__device__ __forceinline__ void mma16816(float* d, const uint32_t* a, const uint32_t* b) {
    asm volatile(
        "mma.sync.aligned.m16n8k16.row.col.f32.f16.f16.f32 "
        "{%0,%1,%2,%3},{%4,%5,%6,%7},{%8,%9},{%0,%1,%2,%3};"
        : "+f"(d[0]), "+f"(d[1]), "+f"(d[2]), "+f"(d[3])
        : "r"(a[0]), "r"(a[1]), "r"(a[2]), "r"(a[3]), "r"(b[0]), "r"(b[1]));
}
__device__ __forceinline__ void ldmx4(uint32_t* r, uint32_t addr) {
    asm volatile("ldmatrix.sync.aligned.m8n8.x4.shared.b16 {%0,%1,%2,%3},[%4];"
                 : "=r"(r[0]), "=r"(r[1]), "=r"(r[2]), "=r"(r[3]) : "r"(addr));
}

__global__ __launch_bounds__(TB, 2)
void conv_mma_min_kernel(const float* __restrict__ x,
                         const float* __restrict__ bias,
                         float* __restrict__ out)
{
    extern __shared__ __align__(128) char smem[];
    const uint32_t sb = (uint32_t)__cvta_generic_to_shared(smem);
    const int tid  = threadIdx.x;
    const int lane = tid & 31;
    const int warp = tid >> 5;
    const int wm   = warp >> 1;           // 0..3 : M slice (32 px)
    const int wn   = warp & 1;            // 0..1 : N half (64 oc)

    const int gx0 = blockIdx.x * TW;
    const int gy0 = blockIdx.y * TH;
    const int bt  = blockIdx.z;
    const float* xb = x + (size_t)bt * C_ * H_ * W_;

    if (tid < 32)
        *(float4*)(smem + SM_BIAS + tid * 16) = *(const float4*)(bias + tid * 4);

    // ---- stage input patch: fp32 -> fp16 ----
    for (int i = tid; i < C_ * PH * PW; i += TB) {
        int ic  = i / (PH * PW);
        int pix = i - ic * (PH * PW);
        int yy  = pix / PW;
        int xx  = pix - yy * PW;
        int gy = gy0 + yy, gx = gx0 + xx;
        float v = 0.f;
        if (gy < H_ && gx < W_)
            v = __ldg(xb + ((size_t)ic * H_ + gy) * W_ + gx);
        *(__half*)(smem + SM_PATCH + yy * YSTRIDE + xx * XSTRIDE + ic * 2) = __float2half(v);
    }
    __syncthreads();                       // patch visible; only sync before epilogue

    float d[2][8][4];
    #pragma unroll
    for (int mt = 0; mt < 2; mt++)
        #pragma unroll
        for (int nt = 0; nt < 8; nt++)
            #pragma unroll
            for (int j = 0; j < 4; j++) d[mt][nt][j] = 0.f;

    const int arow = 2 * wm;
    const int acol = lane & 15;
    const uint32_t asel = (uint32_t)(lane >> 4) * 16;

    #pragma unroll 1
    for (int c = 0; c < 9; ++c) {
        const int ky = c / 3, kx = c - 3 * ky;
        const uint32_t abase = sb + SM_PATCH
                             + (uint32_t)(arow + ky) * YSTRIDE
                             + (uint32_t)(acol + kx) * XSTRIDE + asel;
        const __half* bp = g_wfrag
            + (((size_t)c * 4) * 16 + wn * 8) * 32 * 4 + lane * 4;

        #pragma unroll
        for (int kc = 0; kc < 4; kc++) {
            uint32_t ah0[4], ah1[4];
            ldmx4(ah0, abase + kc * 32);
            ldmx4(ah1, abase + kc * 32 + YSTRIDE);
            // batch all B fragments for this kc first: MLP=8 toward L2
            const __half* bk = bp + (size_t)kc * 16 * 32 * 4;
            uint2 bf[8];
            #pragma unroll
            for (int nt = 0; nt < 8; nt++)
                bf[nt] = __ldg((const uint2*)(bk + nt * 128));
            #pragma unroll
            for (int nt = 0; nt < 8; nt++) {
                mma16816(d[0][nt], ah0, (const uint32_t*)&bf[nt]);
                mma16816(d[1][nt], ah1, (const uint32_t*)&bf[nt]);
            }
        }
    }

    // ---- epilogue: min over 128 oc (+bias), then *2 ----
    const int q = lane & 3;
    const int r = lane >> 2;
    float bpair[8][2];
    #pragma unroll
    for (int nt = 0; nt < 8; nt++) {
        int c0 = wn * 64 + nt * 8 + q * 2;
        const float* bs = (const float*)(smem + SM_BIAS);
        bpair[nt][0] = bs[c0];
        bpair[nt][1] = bs[c0 + 1];
    }
    #pragma unroll
    for (int mt = 0; mt < 2; mt++) {
        #pragma unroll
        for (int rh = 0; rh < 2; rh++) {
            float m = FLT_MAX;
            #pragma unroll
            for (int nt = 0; nt < 8; nt++) {
                m = fminf(m, d[mt][nt][2 * rh]     + bpair[nt][0]);
                m = fminf(m, d[mt][nt][2 * rh + 1] + bpair[nt][1]);
            }
            m = fminf(m, __shfl_xor_sync(0xffffffffu, m, 1));
            m = fminf(m, __shfl_xor_sync(0xffffffffu, m, 2));
            if (q == 0) {
                int px = r + 8 * rh;
                int py = 2 * wm + mt;
                ((float*)(smem + SM_RED))[(py * 16 + px) * 2 + wn] = m;
            }
        }
    }
    __syncthreads();
    if (tid < 128) {
        int py = tid >> 4, px = tid & 15;
        int oy = gy0 + py, ox = gx0 + px;
        if (oy < OH_ && ox < OW_) {
            const float* red = (const float*)(smem + SM_RED);
            float m = fminf(red[tid * 2], red[tid * 2 + 1]);
            out[((size_t)bt * OH_ + oy) * OW_ + ox] = 2.0f * m;
        }
    }
}

extern "C" void kernel_launch(void* const* d_in, const int* in_sizes, int n_in,
                              void* d_out, int out_size)
{
    const float* x    = (const float*)d_in[0];   // (16,64,256,256)
    const float* w    = (const float*)d_in[1];   // (128,64,3,3)
    const float* bias = (const float*)d_in[2];   // (128,)
    float* out = (float*)d_out;                  // (16,1,254,254)

    cudaFuncSetAttribute(conv_mma_min_kernel,
                         cudaFuncAttributeMaxDynamicSharedMemorySize, SMEM_TOTAL);

    prep_weights_kernel<<<(W_FRAGS + 255) / 256, 256>>>(w);

    dim3 grid(16, 32, B_);   // x-tiles, y-tiles, batch
    conv_mma_min_kernel<<<grid, TB, SMEM_TOTAL>>>(x, bias, out);
    (void)in_sizes; (void)n_in; (void)out_size;
}

// round 15
// speedup vs baseline: 10.6065x; 1.7271x over previous
#include <cuda_runtime.h>
#include <cuda_fp16.h>
#include <float.h>
#include <stdint.h>

#define B_   16
#define C_   64
#define H_   256
#define W_   256
#define OC_  128
#define OH_  254
#define OW_  254

#define TW   16      // tile width (px)
#define TH   8       // tile height (px) -> M = 128
#define PW   20      // patch width incl. halo
#define PH   10      // patch height incl. halo
#define TB   256     // 8 warps
#define GRID 304     // persistent, 2 CTAs/SM on GB300 (152 SMs)
#define NTX  16
#define NTY  32
#define NT   (B_ * NTX * NTY)   // 8192

#define XP   260     // padded NHWC extent (halo zeroed)

// patch smem: [y][x][ic] fp16, x-stride 144B (128B payload + 16B anti-conflict pad)
#define XSTRIDE    144
#define YSTRIDE    (PW * XSTRIDE)          // 2880
#define PATCH_SZ   (PH * YSTRIDE)          // 28800
#define SM_BIAS    0                       // 512 B
#define SM_RED     512                     // 1024 B
#define SM_PATCH   1536
#define SMEM_TOTAL (SM_PATCH + 2 * PATCH_SZ)   // 59136 -> 2 CTAs/SM

// fp16 NHWC padded input: [b][y][x][ic]
__device__ __align__(16) __half g_xh[(size_t)B_ * XP * XP * C_];   // 138 MB

// weights fp16, per-lane fragment order: [pos][kc(4)][nt(16)][lane(32)][4]
#define W_FRAGS (9 * 4 * 16 * 32)
__device__ __align__(16) __half g_wfrag[W_FRAGS * 4];

// ---- prep 1: zero the padded halo (x>=256 or y>=256) ----
__global__ void zero_halo_kernel() {
    int t = blockIdx.x * blockDim.x + threadIdx.x;   // over 16*260*260 px
    if (t >= B_ * XP * XP) return;
    int b = t / (XP * XP);
    int r = t - b * (XP * XP);
    int y = r / XP;
    int x = r - y * XP;
    if (y < H_ && x < W_) return;
    uint4 z = make_uint4(0, 0, 0, 0);
    uint4* p = (uint4*)(g_xh + (size_t)t * C_);
    #pragma unroll
    for (int i = 0; i < 8; i++) p[i] = z;
}

// ---- prep 2: NCHW fp32 -> NHWC fp16 transpose (smem-tiled) ----
__global__ __launch_bounds__(256)
void transpose_kernel(const float* __restrict__ x) {
    __shared__ __half s[64 * 72];          // [px][ic], pitch 72 halves (144B)
    const int x0 = blockIdx.x * 64;
    const int y  = blockIdx.y;
    const int b  = blockIdx.z;
    const int tid = threadIdx.x;
    // read: coalesced along x per ic
    #pragma unroll
    for (int k = 0; k < 16; k++) {
        int idx = tid + k * 256;           // 4096 = 64 ic * 64 px
        int ic = idx >> 6;
        int xo = idx & 63;
        float v = __ldg(x + (((size_t)b * C_ + ic) * H_ + y) * W_ + x0 + xo);
        s[xo * 72 + ic] = __float2half(v);
    }
    __syncthreads();
    // write: 128B contiguous per px, coalesced
    #pragma unroll
    for (int k = 0; k < 2; k++) {
        int idx = tid + k * 256;           // 512 = 64 px * 8 uint4
        int px = idx >> 3;
        int q  = idx & 7;
        uint4 v = *(const uint4*)(s + px * 72 + q * 8);
        *(uint4*)(g_xh + ((((size_t)b * XP) + y) * XP + x0 + px) * C_ + q * 8) = v;
    }
}

__global__ void prep_weights_kernel(const float* __restrict__ w) {
    int i = blockIdx.x * blockDim.x + threadIdx.x;
    if (i >= W_FRAGS) return;
    int lane = i & 31;
    int nt   = (i >> 5) & 15;
    int kc   = (i >> 9) & 3;
    int pos  = i >> 11;
    int oc   = nt * 8 + (lane >> 2);
    int kk0  = (lane & 3) * 2;
    int ics[4] = { kc*16 + kk0, kc*16 + kk0 + 1, kc*16 + kk0 + 8, kc*16 + kk0 + 9 };
    __half outv[4];
    #pragma unroll
    for (int j = 0; j < 4; j++)
        outv[j] = __float2half(w[((size_t)oc * C_ + ics[j]) * 9 + pos]);
    *(uint2*)(&g_wfrag[(size_t)i * 4]) = *(uint2*)outv;
}

__device__ __forceinline__ void mma16816(float* d, const uint32_t* a, const uint32_t* b) {
    asm volatile(
        "mma.sync.aligned.m16n8k16.row.col.f32.f16.f16.f32 "
        "{%0,%1,%2,%3},{%4,%5,%6,%7},{%8,%9},{%0,%1,%2,%3};"
        : "+f"(d[0]), "+f"(d[1]), "+f"(d[2]), "+f"(d[3])
        : "r"(a[0]), "r"(a[1]), "r"(a[2]), "r"(a[3]), "r"(b[0]), "r"(b[1]));
}
__device__ __forceinline__ void ldmx4(uint32_t* r, uint32_t addr) {
    asm volatile("ldmatrix.sync.aligned.m8n8.x4.shared.b16 {%0,%1,%2,%3},[%4];"
                 : "=r"(r[0]), "=r"(r[1]), "=r"(r[2]), "=r"(r[3]) : "r"(addr));
}
__device__ __forceinline__ void cp16(uint32_t dst, const void* src) {
    asm volatile("cp.async.cg.shared.global [%0], [%1], 16;" :: "r"(dst), "l"(src));
}

__global__ __launch_bounds__(TB, 2)
void conv_mma_min_kernel(const float* __restrict__ bias,
                         float* __restrict__ out)
{
    extern __shared__ __align__(128) char smem[];
    const uint32_t sb = (uint32_t)__cvta_generic_to_shared(smem);
    const int tid  = threadIdx.x;
    const int lane = tid & 31;
    const int warp = tid >> 5;
    const int wm   = warp >> 1;           // 0..3 : M slice (32 px)
    const int wn   = warp & 1;            // 0..1 : N half (64 oc)

    if (tid < 32)
        *(float4*)(smem + SM_BIAS + tid * 16) = *(const float4*)(bias + tid * 4);

    // ---- async patch stage from NHWC fp16 (1600 x 16B granules) ----
    auto stage = [&](int t, int buf) {
        const int bt  = t >> 9;
        const int rem = t & 511;
        const int gy0 = (rem >> 4) * TH;
        const int gx0 = (rem & 15) * TW;
        const __half* base = g_xh + (((size_t)bt * XP + gy0) * XP + gx0) * C_;
        const uint32_t db = sb + SM_PATCH + buf * PATCH_SZ;
        #pragma unroll
        for (int k = 0; k < 7; k++) {
            int g = tid + k * TB;
            if (g < 1600) {
                int y   = g / 160;
                int r2  = g - y * 160;
                int xx  = r2 >> 3;
                int i   = r2 & 7;
                cp16(db + y * YSTRIDE + xx * XSTRIDE + i * 16,
                     base + ((size_t)y * XP + xx) * C_ + i * 8);
            }
        }
        asm volatile("cp.async.commit_group;");
    };

    const int arow = 2 * wm;
    const int acol = lane & 15;
    const uint32_t asel = (uint32_t)(lane >> 4) * 16;
    const int q = lane & 3;
    const int r = lane >> 2;

    float bpair[8][2];
    #pragma unroll
    for (int nt = 0; nt < 8; nt++) {
        int c0 = wn * 64 + nt * 8 + q * 2;
        bpair[nt][0] = __ldg(bias + c0);
        bpair[nt][1] = __ldg(bias + c0 + 1);
    }

    int buf = 0;
    stage(blockIdx.x, 0);

    for (int t = blockIdx.x; t < NT; t += GRID) {
        asm volatile("cp.async.wait_group 0;");
        __syncthreads();                      // patch[buf] visible to all
        if (t + GRID < NT) stage(t + GRID, buf ^ 1);   // overlaps MMA below

        float d[2][8][4];
        #pragma unroll
        for (int mt = 0; mt < 2; mt++)
            #pragma unroll
            for (int nt = 0; nt < 8; nt++)
                #pragma unroll
                for (int j = 0; j < 4; j++) d[mt][nt][j] = 0.f;

        const uint32_t pbase = sb + SM_PATCH + buf * PATCH_SZ;

        #pragma unroll 1
        for (int c = 0; c < 9; ++c) {
            const int ky = c / 3, kx = c - 3 * ky;
            const uint32_t abase = pbase
                                 + (uint32_t)(arow + ky) * YSTRIDE
                                 + (uint32_t)(acol + kx) * XSTRIDE + asel;
            const __half* bp = g_wfrag + (((size_t)c * 4) * 16 + wn * 8) * 128 + lane * 4;

            #pragma unroll
            for (int kc = 0; kc < 4; kc++) {
                uint32_t ah0[4], ah1[4];
                ldmx4(ah0, abase + kc * 32);
                ldmx4(ah1, abase + kc * 32 + YSTRIDE);
                const __half* bk = bp + (size_t)kc * 2048;
                uint2 bf[8];
                #pragma unroll
                for (int nt = 0; nt < 8; nt++)
                    bf[nt] = __ldg((const uint2*)(bk + nt * 128));
                #pragma unroll
                for (int nt = 0; nt < 8; nt++) {
                    mma16816(d[0][nt], ah0, (const uint32_t*)&bf[nt]);
                    mma16816(d[1][nt], ah1, (const uint32_t*)&bf[nt]);
                }
            }
        }

        // ---- epilogue: min over 128 oc (+bias), then *2 ----
        #pragma unroll
        for (int mt = 0; mt < 2; mt++) {
            #pragma unroll
            for (int rh = 0; rh < 2; rh++) {
                float m = FLT_MAX;
                #pragma unroll
                for (int nt = 0; nt < 8; nt++) {
                    m = fminf(m, d[mt][nt][2 * rh]     + bpair[nt][0]);
                    m = fminf(m, d[mt][nt][2 * rh + 1] + bpair[nt][1]);
                }
                m = fminf(m, __shfl_xor_sync(0xffffffffu, m, 1));
                m = fminf(m, __shfl_xor_sync(0xffffffffu, m, 2));
                if (q == 0) {
                    int px = r + 8 * rh;
                    int py = 2 * wm + mt;
                    ((float*)(smem + SM_RED))[(py * 16 + px) * 2 + wn] = m;
                }
            }
        }
        __syncthreads();
        if (tid < 128) {
            const int bt  = t >> 9;
            const int rem = t & 511;
            const int gy0 = (rem >> 4) * TH;
            const int gx0 = (rem & 15) * TW;
            int py = tid >> 4, px = tid & 15;
            int oy = gy0 + py, ox = gx0 + px;
            if (oy < OH_ && ox < OW_) {
                const float* red = (const float*)(smem + SM_RED);
                float m = fminf(red[tid * 2], red[tid * 2 + 1]);
                out[((size_t)bt * OH_ + oy) * OW_ + ox] = 2.0f * m;
            }
        }
        buf ^= 1;
    }
}

extern "C" void kernel_launch(void* const* d_in, const int* in_sizes, int n_in,
                              void* d_out, int out_size)
{
    const float* x    = (const float*)d_in[0];   // (16,64,256,256)
    const float* w    = (const float*)d_in[1];   // (128,64,3,3)
    const float* bias = (const float*)d_in[2];   // (128,)
    float* out = (float*)d_out;                  // (16,1,254,254)

    cudaFuncSetAttribute(conv_mma_min_kernel,
                         cudaFuncAttributeMaxDynamicSharedMemorySize, SMEM_TOTAL);

    zero_halo_kernel<<<(B_ * XP * XP + 255) / 256, 256>>>();
    {
        dim3 tg(4, 256, B_);                 // x-tiles(64), y, batch
        transpose_kernel<<<tg, 256>>>(x);
    }
    prep_weights_kernel<<<(W_FRAGS + 255) / 256, 256>>>(w);

    conv_mma_min_kernel<<<GRID, TB, SMEM_TOTAL>>>(bias, out);
    (void)in_sizes; (void)n_in; (void)out_size;
}

// round 16
// speedup vs baseline: 11.6600x; 1.0993x over previous
#include <cuda_runtime.h>
#include <cuda_fp16.h>
#include <float.h>
#include <stdint.h>

#define B_   16
#define C_   64
#define H_   256
#define W_   256
#define OC_  128
#define OH_  254
#define OW_  254

#define TW   16      // tile width (px)
#define TH   16      // tile height (px) -> M = 256
#define PW   18      // patch width incl. halo
#define PH   18      // patch height incl. halo
#define TB   512     // 16 warps
#define GRID 152     // persistent, 1 CTA/SM
#define NT   (B_ * 16 * 16)   // 4096 tiles

#define XP   260     // padded NHWC extent (halo zeroed)

// patch smem: [y][x][ic] fp16, 128B per (y,x), bank-conflict-free via XOR swizzle
#define ROWB       128
#define YSTRIDE    (PW * ROWB)             // 2304
#define PATCH_SZ   (PH * YSTRIDE)          // 41472
#define SM_RED     0                       // 256 px * 2 * 4B = 2048
#define SM_PATCH   2048
#define SM_B       (SM_PATCH + 2 * PATCH_SZ)   // 84992
#define B_BYTES    147456                  // 9*4*16*32*4 fragments * 8B
#define SMEM_TOTAL (SM_B + B_BYTES)        // 232448 == 227 KB max dynamic smem

// fp16 NHWC padded input: [b][y][x][ic]
__device__ __align__(16) __half g_xh[(size_t)B_ * XP * XP * C_];   // 138 MB

// weights fp16, per-lane fragment order: [pos][kc(4)][nt(16)][lane(32)][4]
#define W_FRAGS (9 * 4 * 16 * 32)
__device__ __align__(16) __half g_wfrag[W_FRAGS * 4];

__global__ void zero_halo_kernel() {
    int t = blockIdx.x * blockDim.x + threadIdx.x;
    if (t >= B_ * XP * XP) return;
    int b = t / (XP * XP);
    int r = t - b * (XP * XP);
    int y = r / XP;
    int x = r - y * XP;
    if (y < H_ && x < W_) return;
    uint4 z = make_uint4(0, 0, 0, 0);
    uint4* p = (uint4*)(g_xh + (size_t)t * C_);
    #pragma unroll
    for (int i = 0; i < 8; i++) p[i] = z;
}

__global__ __launch_bounds__(256)
void transpose_kernel(const float* __restrict__ x) {
    __shared__ __half s[64 * 72];
    const int x0 = blockIdx.x * 64;
    const int y  = blockIdx.y;
    const int b  = blockIdx.z;
    const int tid = threadIdx.x;
    #pragma unroll
    for (int k = 0; k < 16; k++) {
        int idx = tid + k * 256;
        int ic = idx >> 6;
        int xo = idx & 63;
        float v = __ldg(x + (((size_t)b * C_ + ic) * H_ + y) * W_ + x0 + xo);
        s[xo * 72 + ic] = __float2half(v);
    }
    __syncthreads();
    #pragma unroll
    for (int k = 0; k < 2; k++) {
        int idx = tid + k * 256;
        int px = idx >> 3;
        int q  = idx & 7;
        uint4 v = *(const uint4*)(s + px * 72 + q * 8);
        *(uint4*)(g_xh + ((((size_t)b * XP) + y) * XP + x0 + px) * C_ + q * 8) = v;
    }
}

__global__ void prep_weights_kernel(const float* __restrict__ w) {
    int i = blockIdx.x * blockDim.x + threadIdx.x;
    if (i >= W_FRAGS) return;
    int lane = i & 31;
    int nt   = (i >> 5) & 15;
    int kc   = (i >> 9) & 3;
    int pos  = i >> 11;
    int oc   = nt * 8 + (lane >> 2);
    int kk0  = (lane & 3) * 2;
    int ics[4] = { kc*16 + kk0, kc*16 + kk0 + 1, kc*16 + kk0 + 8, kc*16 + kk0 + 9 };
    __half outv[4];
    #pragma unroll
    for (int j = 0; j < 4; j++)
        outv[j] = __float2half(w[((size_t)oc * C_ + ics[j]) * 9 + pos]);
    *(uint2*)(&g_wfrag[(size_t)i * 4]) = *(uint2*)outv;
}

__device__ __forceinline__ void mma16816(float* d, const uint32_t* a, const uint32_t* b) {
    asm volatile(
        "mma.sync.aligned.m16n8k16.row.col.f32.f16.f16.f32 "
        "{%0,%1,%2,%3},{%4,%5,%6,%7},{%8,%9},{%0,%1,%2,%3};"
        : "+f"(d[0]), "+f"(d[1]), "+f"(d[2]), "+f"(d[3])
        : "r"(a[0]), "r"(a[1]), "r"(a[2]), "r"(a[3]), "r"(b[0]), "r"(b[1]));
}
__device__ __forceinline__ void ldmx4(uint32_t* r, uint32_t addr) {
    asm volatile("ldmatrix.sync.aligned.m8n8.x4.shared.b16 {%0,%1,%2,%3},[%4];"
                 : "=r"(r[0]), "=r"(r[1]), "=r"(r[2]), "=r"(r[3]) : "r"(addr));
}
__device__ __forceinline__ void cp16(uint32_t dst, const void* src) {
    asm volatile("cp.async.cg.shared.global [%0], [%1], 16;" :: "r"(dst), "l"(src));
}

__global__ __launch_bounds__(TB, 1)
void conv_mma_min_kernel(const float* __restrict__ bias,
                         float* __restrict__ out)
{
    extern __shared__ __align__(128) char smem[];
    const uint32_t sb = (uint32_t)__cvta_generic_to_shared(smem);
    const int tid  = threadIdx.x;
    const int lane = tid & 31;
    const int warp = tid >> 5;
    const int wm   = warp >> 1;           // 0..7 : M slice (32 px)
    const int wn   = warp & 1;            // 0..1 : N half (64 oc)

    // ---- one-time: weights into smem (fragment-ordered, straight copy) ----
    for (int j = tid; j < B_BYTES / 16; j += TB)
        cp16(sb + SM_B + j * 16, (const char*)g_wfrag + (size_t)j * 16);

    // ---- async patch stage from NHWC fp16 (2592 x 16B granules, swizzled) ----
    auto stage = [&](int t, int buf) {
        const int bt  = t >> 8;
        const int rem = t & 255;
        const int gy0 = (rem >> 4) * TH;
        const int gx0 = (rem & 15) * TW;
        const __half* base = g_xh + (((size_t)bt * XP + gy0) * XP + gx0) * C_;
        const uint32_t db = sb + SM_PATCH + buf * PATCH_SZ;
        #pragma unroll
        for (int k = 0; k < 6; k++) {
            int g = tid + k * TB;
            if (g < PH * PW * 8) {
                int y  = g / (PW * 8);
                int r2 = g - y * (PW * 8);
                int xx = r2 >> 3;
                int i  = r2 & 7;
                cp16(db + y * YSTRIDE + xx * ROWB + ((i * 16) ^ ((xx & 7) * 16)),
                     base + ((size_t)y * XP + xx) * C_ + i * 8);
            }
        }
    };

    const int arow = 2 * wm;
    const int acol = lane & 15;
    const uint32_t chunk16 = (uint32_t)(lane >> 4) * 16;
    const int q = lane & 3;
    const int r = lane >> 2;

    float bpair[8][2];
    #pragma unroll
    for (int nt = 0; nt < 8; nt++) {
        int c0 = wn * 64 + nt * 8 + q * 2;
        bpair[nt][0] = __ldg(bias + c0);
        bpair[nt][1] = __ldg(bias + c0 + 1);
    }

    int buf = 0;
    stage(blockIdx.x, 0);
    asm volatile("cp.async.commit_group;");

    for (int t = blockIdx.x; t < NT; t += GRID) {
        asm volatile("cp.async.wait_group 0;");
        __syncthreads();                      // patch[buf] (+B on first iter) visible
        if (t + GRID < NT) {
            stage(t + GRID, buf ^ 1);         // overlaps MMA below
            asm volatile("cp.async.commit_group;");
        }

        float d[2][8][4];
        #pragma unroll
        for (int mt = 0; mt < 2; mt++)
            #pragma unroll
            for (int nt = 0; nt < 8; nt++)
                #pragma unroll
                for (int j = 0; j < 4; j++) d[mt][nt][j] = 0.f;

        const uint32_t pbase = sb + SM_PATCH + buf * PATCH_SZ;

        #pragma unroll 1
        for (int c = 0; c < 9; ++c) {
            const int ky = c / 3, kx = c - 3 * ky;
            const int xl = acol + kx;
            const uint32_t s7 = (uint32_t)(xl & 7) * 16;
            const uint32_t rowbase = pbase + (uint32_t)(arow + ky) * YSTRIDE
                                   + (uint32_t)xl * ROWB;
            const char* bsm = smem + SM_B + ((size_t)(c * 4) * 16 + wn * 8) * 256 + lane * 8;

            #pragma unroll
            for (int kc = 0; kc < 4; kc++) {
                uint32_t aoff = (chunk16 + (uint32_t)kc * 32) ^ s7;
                uint32_t ah0[4], ah1[4];
                ldmx4(ah0, rowbase + aoff);
                ldmx4(ah1, rowbase + YSTRIDE + aoff);
                const char* bk = bsm + (size_t)kc * 4096;   // 16 nt * 256B
                uint2 bf[8];
                #pragma unroll
                for (int nt = 0; nt < 8; nt++)
                    bf[nt] = *(const uint2*)(bk + nt * 256);
                #pragma unroll
                for (int nt = 0; nt < 8; nt++) {
                    mma16816(d[0][nt], ah0, (const uint32_t*)&bf[nt]);
                    mma16816(d[1][nt], ah1, (const uint32_t*)&bf[nt]);
                }
            }
        }

        // ---- epilogue: min over 128 oc (+bias), then *2 ----
        #pragma unroll
        for (int mt = 0; mt < 2; mt++) {
            #pragma unroll
            for (int rh = 0; rh < 2; rh++) {
                float m = FLT_MAX;
                #pragma unroll
                for (int nt = 0; nt < 8; nt++) {
                    m = fminf(m, d[mt][nt][2 * rh]     + bpair[nt][0]);
                    m = fminf(m, d[mt][nt][2 * rh + 1] + bpair[nt][1]);
                }
                m = fminf(m, __shfl_xor_sync(0xffffffffu, m, 1));
                m = fminf(m, __shfl_xor_sync(0xffffffffu, m, 2));
                if (q == 0) {
                    int px = r + 8 * rh;
                    int py = 2 * wm + mt;
                    ((float*)(smem + SM_RED))[(py * 16 + px) * 2 + wn] = m;
                }
            }
        }
        __syncthreads();
        if (tid < 256) {
            const int bt  = t >> 8;
            const int rem = t & 255;
            const int gy0 = (rem >> 4) * TH;
            const int gx0 = (rem & 15) * TW;
            int py = tid >> 4, px = tid & 15;
            int oy = gy0 + py, ox = gx0 + px;
            if (oy < OH_ && ox < OW_) {
                const float* red = (const float*)(smem + SM_RED);
                float m = fminf(red[tid * 2], red[tid * 2 + 1]);
                out[((size_t)bt * OH_ + oy) * OW_ + ox] = 2.0f * m;
            }
        }
        buf ^= 1;
        // next-iter top __syncthreads orders RED reads before next writes
    }
}

extern "C" void kernel_launch(void* const* d_in, const int* in_sizes, int n_in,
                              void* d_out, int out_size)
{
    const float* x    = (const float*)d_in[0];   // (16,64,256,256)
    const float* w    = (const float*)d_in[1];   // (128,64,3,3)
    const float* bias = (const float*)d_in[2];   // (128,)
    float* out = (float*)d_out;                  // (16,1,254,254)

    cudaFuncSetAttribute(conv_mma_min_kernel,
                         cudaFuncAttributeMaxDynamicSharedMemorySize, SMEM_TOTAL);

    zero_halo_kernel<<<(B_ * XP * XP + 255) / 256, 256>>>();
    {
        dim3 tg(4, 256, B_);
        transpose_kernel<<<tg, 256>>>(x);
    }
    prep_weights_kernel<<<(W_FRAGS + 255) / 256, 256>>>(w);

    conv_mma_min_kernel<<<GRID, TB, SMEM_TOTAL>>>(bias, out);
    (void)in_sizes; (void)n_in; (void)out_size;
}